// round 13
// baseline (speedup 1.0000x reference)
#include <cuda_runtime.h>

#define HH 4096
#define WW 1024
#define SS 16
#define NSEG 17
#define NCHB 8            // row-blocks per column (512 rows each)
#define WIN 12.0f
#define FINF 3.0e38f

// ---- scratch (__device__ globals; zero-initialized, no allocation) ---------
__device__ float g_bsum[NCHB * WW];       // per-(row-block, column) sums
__device__ unsigned g_flag[256];          // [bw*8+bh] pass-1 publish flags
__device__ float g_mag[WW];               // per-column total mass
__device__ float g_cum[HH * WW];          // normalized cumsum (window rows only)
// hard partials, dense layout [bh][s][w]
__device__ float g_hB[NCHB * NSEG * WW];
__device__ float g_hA[NCHB * NSEG * WW];
__device__ float g_hC[NCHB * NSEG * WW];
__device__ float g_sum, g_cnt;
__device__ unsigned g_cnt2, g_ticket;

// data-independent per-segment reference (bit-identical everywhere)
__device__ __forceinline__ float seg_ref(float sL, float sR) {
    return (sL + sR) * (0.5f / (float)HH);
}

// ---------------------------------------------------------------------------
// Single fused kernel. 256 blocks (bw 0..31, bh 0..7), all co-resident.
//   Phase 1: block-column sums -> g_bsum, flag sync within column group.
//   Phase 2: normalized cumsum scan; predicated g_cum stores (window rows
//            only); hard segment moments about snake-derived refs -> dense
//            partials. Global counter sync over all 256 blocks.
//   Phase 3: block finalizes 4 columns: 64 sigmoid windows (one scattered
//            load each), 68 segment combines, masked accumulate, ticket
//            finalize + state reset for the next graph replay.
// ---------------------------------------------------------------------------
__global__ void __launch_bounds__(256, 2) k_all(const float* __restrict__ preds,
                                                const float* __restrict__ snakes,
                                                float* __restrict__ out) {
    __shared__ float s_chunk[8][32];
    __shared__ float snk[SS][32];
    __shared__ float accB[NSEG][32], accA[NSEG][32], accC[NSEG][32];
    __shared__ float fw0[4][SS], fw1[4][SS], fw2[4][SS];
    __shared__ float colV[4];

    const int bw = blockIdx.x, bh = blockIdx.y;
    const int bid = bw * NCHB + bh;
    const int tid = threadIdx.x;
    const int v = tid >> 5, lane = tid & 31;
    const int col = bw * 32 + lane;

    if (bid == 0 && tid == 0) { g_sum = 0.f; g_cnt = 0.f; }

    for (int e = tid; e < SS * 32; e += 256)
        snk[e >> 5][e & 31] = snakes[(e >> 5) * WW + bw * 32 + (e & 31)];
    for (int e = tid; e < NSEG * 32; e += 256) {
        accB[e >> 5][e & 31] = 0.f;
        accA[e >> 5][e & 31] = 0.f;
        accC[e >> 5][e & 31] = 0.f;
    }
    if (tid < 4) colV[tid] = 0.f;

    const int h0 = (bh * 8 + v) * 64;
    const float* p = preds + (size_t)h0 * WW + col;

    // ---- phase 1: chunk sums -> block sum -> publish ----
    float csum = 0.f;
#pragma unroll
    for (int b = 0; b < 4; b++) {
        float r0 = 0.f, r1 = 0.f, r2 = 0.f, r3 = 0.f;
#pragma unroll
        for (int k = 0; k < 16; k += 4) {
            r0 += p[(size_t)(b * 16 + k + 0) * WW];
            r1 += p[(size_t)(b * 16 + k + 1) * WW];
            r2 += p[(size_t)(b * 16 + k + 2) * WW];
            r3 += p[(size_t)(b * 16 + k + 3) * WW];
        }
        csum += (r0 + r1) + (r2 + r3);
    }
    s_chunk[v][lane] = csum;
    __syncthreads();

    if (tid < 32) {
        float bsum = 0.f;
#pragma unroll
        for (int v2 = 0; v2 < 8; v2++) bsum += s_chunk[v2][tid];
        g_bsum[bh * WW + bw * 32 + tid] = bsum;
    }
    __syncthreads();
    if (tid == 0) {
        __threadfence();
        atomicExch(&g_flag[bw * NCHB + bh], 1u);
    }
    if (tid < NCHB) {
        volatile unsigned* f = &g_flag[bw * NCHB + tid];
        while (*f == 0u) __nanosleep(20);
        __threadfence();
    }
    __syncthreads();

    // ---- base / mag ----
    float base = 0.f, mag = 0.f;
#pragma unroll
    for (int i = 0; i < NCHB; i++) {
        float bs = g_bsum[i * WW + col];
        base += (i < bh) ? bs : 0.f;
        mag += bs;
    }
#pragma unroll
    for (int v2 = 0; v2 < 8; v2++)
        base += (v2 < v) ? s_chunk[v2][lane] : 0.f;
    const float inv = 1.0f / mag;
    if (bh == 0 && tid < 32) g_mag[col] = mag;

    // ---- phase 2: scan + predicated g_cum + hard moments ----
    float* outc = g_cum + (size_t)h0 * WW + col;

    int j = 0;
    while (j < SS && snk[j][lane] <= (float)h0) j++;
    float sL = (j > 0) ? snk[j - 1][lane] : 0.f;
    float sR = (j < SS) ? snk[j][lane] : (float)HH;
    float ref = seg_ref(sL, sR);
    float sNext = (j < SS) ? sR : FINF;

    float cum = base;
    float A = 0.f, C = 0.f, B = 0.f;

#pragma unroll
    for (int b = 0; b < 4; b++) {
        float regs[16];
#pragma unroll
        for (int k = 0; k < 16; k++)
            regs[k] = p[(size_t)(b * 16 + k) * WW];
#pragma unroll
        for (int k = 0; k < 16; k++) {
            const int r = b * 16 + k;
            cum += regs[k];
            const float x = cum * inv;
            const float hf = (float)(h0 + r);
            if (hf >= sNext) {                       // segment crossed
                if (B > 0.f) {
                    atomicAdd(&accB[j][lane], B);
                    atomicAdd(&accA[j][lane], A);
                    atomicAdd(&accC[j][lane], C);
                }
                A = C = B = 0.f;
                j++;
                while (j < SS && snk[j][lane] <= hf) j++;
                sL = snk[j - 1][lane];
                sR = (j < SS) ? snk[j][lane] : (float)HH;
                ref = seg_ref(sL, sR);
                sNext = (j < SS) ? sR : FINF;
            }
            // store only rows that the window pass will read
            if ((hf - sL <= WIN) || (sNext - hf <= WIN))
                outc[(size_t)r * WW] = x;
            float dx = x - ref;
            A += dx; C = fmaf(dx, dx, C); B += 1.f;
        }
    }
    if (B > 0.f) {
        atomicAdd(&accB[j][lane], B);
        atomicAdd(&accA[j][lane], A);
        atomicAdd(&accC[j][lane], C);
    }
    __syncthreads();

    // dense coalesced partial write: [bh][s][w]
    for (int e = tid; e < NSEG * 32; e += 256) {
        int s = e >> 5, l = e & 31;
        size_t o = ((size_t)bh * NSEG + s) * WW + bw * 32 + l;
        g_hB[o] = accB[s][l];
        g_hA[o] = accA[s][l];
        g_hC[o] = accC[s][l];
    }
    __syncthreads();

    // ---- global sync #2: all 256 blocks done with phase 2 ----
    if (tid == 0) {
        __threadfence();
        atomicAdd(&g_cnt2, 1u);
        volatile unsigned* c = &g_cnt2;
        while (*c < 256u) __nanosleep(40);
        __threadfence();
    }
    __syncthreads();

    // ---- phase 3: finalize 4 columns (c0..c0+3) ----
    const int c0 = bid * 4;

    // 64 windows, 8 per warp; each window <=25 rows -> one predicated load
#pragma unroll
    for (int i = 0; i < 8; i++) {
        const int win = v * 8 + i;            // 0..63
        const int ci = win >> 4, b = win & 15;
        const int w = c0 + ci;
        const float sp = snk[b][(w & 31)] * 0.f + snakes[b * WW + w]; // direct load
        const int lo = max(0, (int)ceilf(sp - WIN));
        const int hi = min(HH, (int)floorf(sp + WIN) + 1);
        const int h = lo + lane;
        float d0 = 0.f, d1 = 0.f, d2 = 0.f;
        if (h < hi) {
            float t = sp - (float)h;
            float e = __expf(-fabsf(t));
            float sg = e / (1.f + e);
            float dlt = (t > 0.f) ? -sg : sg;   // sigmoid - step, stable
            float x = g_cum[(size_t)h * WW + w];
            d0 = dlt; d1 = dlt * x; d2 = dlt * x * x;
        }
#pragma unroll
        for (int d = 16; d; d >>= 1) {
            d0 += __shfl_xor_sync(0xffffffffu, d0, d);
            d1 += __shfl_xor_sync(0xffffffffu, d1, d);
            d2 += __shfl_xor_sync(0xffffffffu, d2, d);
        }
        if (lane == 0) { fw0[ci][b] = d0; fw1[ci][b] = d1; fw2[ci][b] = d2; }
    }
    __syncthreads();

    // 68 segment combines (4 cols x 17 segs)
    if (tid < 4 * NSEG) {
        const int ci = tid / NSEG, s = tid - ci * NSEG;
        const int w = c0 + ci;
        float B2 = 0.f, A2 = 0.f, C2 = 0.f;
#pragma unroll
        for (int bh2 = 0; bh2 < NCHB; bh2++) {
            size_t idx = ((size_t)bh2 * NSEG + s) * WW + w;
            B2 += g_hB[idx]; A2 += g_hA[idx]; C2 += g_hC[idx];
        }
        float sL2 = (s > 0)  ? snakes[(s - 1) * WW + w] : 0.f;
        float sR2 = (s < SS) ? snakes[s * WW + w]       : (float)HH;
        float ref2 = seg_ref(sL2, sR2);

        float mean = ref2, M2 = 0.f;
        if (B2 > 0.f) { mean = ref2 + A2 / B2; M2 = C2 - A2 * A2 / B2; }

        float D0 = 0.f, D1 = 0.f, D2 = 0.f;
        if (s < SS) { D0 += fw0[ci][s]; D1 += fw1[ci][s]; D2 += fw2[ci][s]; }
        if (s > 0)  { D0 -= fw0[ci][s - 1]; D1 -= fw1[ci][s - 1]; D2 -= fw2[ci][s - 1]; }

        float d1c = D1 - mean * D0;
        float d2c = D2 - 2.f * mean * D1 + mean * mean * D0;
        float Bt = B2 + D0;
        float V = (Bt > 1e-12f) ? (M2 + d2c) - d1c * d1c / Bt : 0.f;
        atomicAdd(&colV[ci], V);
    }
    __syncthreads();

    if (tid < 4) {
        const int w = c0 + tid;
        bool mask = g_mag[w] > 1.0f;
        atomicAdd(&g_sum, mask ? colV[tid] : 0.f);
        atomicAdd(&g_cnt, mask ? 1.f : 0.f);
    }
    __syncthreads();
    if (tid == 0) {
        __threadfence();
        unsigned t = atomicAdd(&g_ticket, 1u);
        if (t == 255u) {                      // last block: finalize + reset
            out[0] = g_sum / ((float)(NSEG * HH)) / g_cnt;
            for (int i = 0; i < 256; i++) g_flag[i] = 0u;
            g_cnt2 = 0u;
            g_ticket = 0u;
            __threadfence();
        }
    }
}

// ---------------------------------------------------------------------------
extern "C" void kernel_launch(void* const* d_in, const int* in_sizes, int n_in,
                              void* d_out, int out_size) {
    const float* snakes = (const float*)d_in[0];   // [16, 1024]
    const float* preds  = (const float*)d_in[1];   // [4096, 1024]
    (void)in_sizes; (void)n_in; (void)out_size;

    k_all<<<dim3(WW / 32, NCHB), 256>>>(preds, snakes, (float*)d_out);
}